// round 15
// baseline (speedup 1.0000x reference)
#include <cuda_runtime.h>
#include <math_constants.h>

// NNLoss: bidirectional 2-D NN loss via uniform-grid spatial binning.
// Kernel 1: block-local bin; cell-sorted points stored as SoA PAIRS
//           {x0,x1,y0,y1} so LDS.128 yields packed f32x2 operands.
// Kernel 2: staged boxes (3x3 straight-line -> 9x9 -> rings), packed
//           f32x2 distance math + LOP3/IMNMX bits|index argmin.

namespace {
constexpr int   Bc   = 64;
constexpr int   Nc   = 2048;
constexpr int   NSB  = 2 * Bc;            // (set, batch) segments = 128
constexpr int   G    = 64;
constexpr int   G2   = G * G;             // 4096 cells
constexpr int   SST  = G2 + 8;            // starts stride (padded)
constexpr float EXT  = 6.0f;
constexpr float CELL = 2.0f * EXT / G;    // 0.1875
constexpr float INVC = (float)G / (2.0f * EXT);
constexpr int   TPB  = 256;
constexpr int   QCH  = Nc / TPB;          // 8 query chunks per (dir,b)
constexpr unsigned IDXMASK = 2047u;       // low 11 bits carry point index
constexpr unsigned SENTINEL = 0x7F800000u | IDXMASK;  // +INF | idx-sat
}

__device__ unsigned short g_start[NSB * SST];      // exclusive cell starts (+total)
__device__ float4         g_sorted4[NSB * Nc / 2]; // SoA pairs {x0,x1,y0,y1}

__device__ __forceinline__ int cell_of(float v) {
    int c = __float2int_rd((v + EXT) * INVC);
    return min(G - 1, max(0, c));
}

// ---- packed f32x2 helpers ----
__device__ __forceinline__ unsigned long long pk2(float a, float b) {
    unsigned long long r;
    asm("mov.b64 %0, {%1, %2};" : "=l"(r) : "f"(a), "f"(b));
    return r;
}
__device__ __forceinline__ unsigned long long add2(unsigned long long a,
                                                   unsigned long long b) {
    unsigned long long r;
    asm("add.rn.f32x2 %0, %1, %2;" : "=l"(r) : "l"(a), "l"(b));
    return r;
}
__device__ __forceinline__ unsigned long long mul2(unsigned long long a,
                                                   unsigned long long b) {
    unsigned long long r;
    asm("mul.rn.f32x2 %0, %1, %2;" : "=l"(r) : "l"(a), "l"(b));
    return r;
}
__device__ __forceinline__ unsigned long long fma2(unsigned long long a,
                                                   unsigned long long b,
                                                   unsigned long long c) {
    unsigned long long r;
    asm("fma.rn.f32x2 %0, %1, %2, %3;" : "=l"(r) : "l"(a), "l"(b), "l"(c));
    return r;
}
__device__ __forceinline__ void unpk(unsigned long long v,
                                     unsigned& lo, unsigned& hi) {
    asm("mov.b64 {%0, %1}, %2;" : "=r"(lo), "=r"(hi) : "l"(v));
}

// ---------------- Kernel 1: block-local binning ----------------
__global__ __launch_bounds__(TPB)
void bin_kernel(const float* __restrict__ preds,
                const float* __restrict__ targs,
                float* __restrict__ out)
{
    __shared__ unsigned int scnt[G2];      // counts -> scatter cursors
    __shared__ float2 pts[Nc];
    __shared__ unsigned int part[TPB];

    const int sb  = blockIdx.x;            // set*64 + b
    const int set = sb >> 6;
    const int b   = sb & (Bc - 1);
    if (sb == 0 && threadIdx.x == 0) out[0] = 0.0f;

    const float4* src = reinterpret_cast<const float4*>(set ? targs : preds)
                      + (size_t)b * Nc;
#pragma unroll
    for (int i = 0; i < Nc / TPB; ++i) {
        float4 p = src[threadIdx.x + i * TPB];
        pts[threadIdx.x + i * TPB] = make_float2(p.x, p.y);
    }
#pragma unroll
    for (int i = 0; i < G2 / TPB; ++i)
        scnt[threadIdx.x + i * TPB] = 0u;
    __syncthreads();

#pragma unroll
    for (int i = 0; i < Nc / TPB; ++i) {
        float2 p = pts[threadIdx.x + i * TPB];
        atomicAdd(&scnt[cell_of(p.y) * G + cell_of(p.x)], 1u);
    }
    __syncthreads();

    // block exclusive scan of 4096 counters
    unsigned int v[16], sum = 0;
    const int base = threadIdx.x * 16;
#pragma unroll
    for (int i = 0; i < 16; ++i) { v[i] = scnt[base + i]; sum += v[i]; }
    part[threadIdx.x] = sum;
    __syncthreads();
    for (int off = 1; off < TPB; off <<= 1) {
        unsigned int a = (threadIdx.x >= off) ? part[threadIdx.x - off] : 0u;
        __syncthreads();
        if (threadIdx.x >= off) part[threadIdx.x] += a;
        __syncthreads();
    }
    unsigned int run = threadIdx.x ? part[threadIdx.x - 1] : 0u;
    unsigned short* st = g_start + sb * SST;
#pragma unroll
    for (int i = 0; i < 16; ++i) {
        scnt[base + i] = run;                       // scatter cursor
        st[base + i]   = (unsigned short)run;
        run += v[i];
    }
    if (threadIdx.x == TPB - 1) st[G2] = (unsigned short)run;   // 2048
    __syncthreads();

    // scatter into SoA pair layout: point pos -> words (pos>>1)*4 + (pos&1)
    // for x and +2 for y
    float* dstw = reinterpret_cast<float*>(g_sorted4 + (size_t)sb * (Nc / 2));
#pragma unroll
    for (int i = 0; i < Nc / TPB; ++i) {
        float2 p = pts[threadIdx.x + i * TPB];
        unsigned int pos = atomicAdd(&scnt[cell_of(p.y) * G + cell_of(p.x)], 1u);
        int w = ((pos >> 1) << 2) | (pos & 1);
        dstw[w]     = p.x;
        dstw[w + 2] = p.y;
    }
}

// ---------------- Kernel 2: staged-box query, packed math ----------------
__global__ __launch_bounds__(TPB)
void query_kernel(const float* __restrict__ subcoef, float* __restrict__ out)
{
    __shared__ float4 tile4[Nc / 2];             // SoA pairs {x0,x1,y0,y1}
    __shared__ unsigned short sst[G2 + 1];       // cell starts (point indices)
    __shared__ float red[TPB / 32];

    int bid = blockIdx.x;
    const int chunk = bid & (QCH - 1);  bid >>= 3;
    const int b     = bid & (Bc - 1);   bid >>= 6;
    const int dir   = bid;                       // 0: preds->targs, 1: targs->preds
    const int qsb = dir * Bc + b;                // query set (set0 = preds)
    const int dsb = (1 - dir) * Bc + b;          // db set

    {
        const float4* srcp = g_sorted4 + (size_t)dsb * (Nc / 2);
        for (int t = threadIdx.x; t < Nc / 2; t += TPB) tile4[t] = srcp[t];
        for (int t = threadIdx.x; t <= G2; t += TPB)    sst[t]  = g_start[dsb * SST + t];
    }
    __syncthreads();

    // query = own set's sorted point (order-invariant loss; cell-coherent lanes)
    float qx, qy;
    {
        const float* qw = reinterpret_cast<const float*>(
            g_sorted4 + (size_t)qsb * (Nc / 2));
        int i = chunk * TPB + threadIdx.x;
        int w = ((i >> 1) << 2) | (i & 1);
        qx = qw[w]; qy = qw[w + 2];
    }
    const int cx = cell_of(qx), cy = cell_of(qy);
    const unsigned long long nqx2 = pk2(-qx, -qx);
    const unsigned long long nqy2 = pk2(-qy, -qy);

    // packed argmin: high 21 bits truncated d^2 bits, low 11 = point index
    unsigned mn = SENTINEL;

    const ulonglong2* stile = reinterpret_cast<const ulonglong2*>(tile4);
    // paired span scan over point range [j, je), rounded OUTWARD to pair
    // bounds (extra points are genuine db points -> superset min, exact)
    auto scan = [&](int j, int je) {
        int p  = j >> 1;
        int pe = (je + 1) >> 1;
#pragma unroll 2
        for (; p < pe; ++p) {
            ulonglong2 t = stile[p];             // t.x={x0,x1}, t.y={y0,y1}
            unsigned long long dx = add2(t.x, nqx2);
            unsigned long long dy = add2(t.y, nqy2);
            unsigned long long s2 = fma2(dx, dx, mul2(dy, dy));
            unsigned s0, s1; unpk(s2, s0, s1);
            unsigned j0 = (unsigned)(p << 1);
            unsigned pk0 = (s0 & ~IDXMASK) | j0;
            unsigned pk1 = (s1 & ~IDXMASK) | (j0 + 1);
            mn = min(mn, min(pk0, pk1));
        }
    };
    auto box = [&](int r) {
        const int xa = max(cx - r, 0), xb = min(cx + r, G - 1);
        const int ya = max(cy - r, 0), yb = min(cy + r, G - 1);
        for (int y = ya; y <= yb; ++y)
            scan(sst[y * G + xa], sst[y * G + xb + 1]);
    };

    // stage 1: 3x3 box, straight-line 3 rows (clamped dups harmless)
    {
        const int xa = max(cx - 1, 0), xb = min(cx + 1, G - 1);
        const int y0 = max(cy - 1, 0), y2 = min(cy + 1, G - 1);
        scan(sst[y0 * G + xa], sst[y0 * G + xb + 1]);
        scan(sst[cy * G + xa], sst[cy * G + xb + 1]);
        scan(sst[y2 * G + xa], sst[y2 * G + xb + 1]);
    }

    // unscanned cells are Chebyshev >= 2 -> d >= CELL
    float best = __uint_as_float(mn & ~IDXMASK);   // <= true best (truncation)
    if (__any_sync(0xffffffffu, best > CELL * CELL)) {
        if (best > CELL * CELL) {
            // stage 2: 9x9 box. Unscanned -> Chebyshev >= 5 -> d >= 4*CELL.
            box(4);
            best = __uint_as_float(mn & ~IDXMASK);
            float b4 = 4.0f * CELL;
            if (best > b4 * b4) {
                // stage 3 (deep tail): rings from k=5
                for (int k = 5; k < G; ++k) {
                    float bd = (float)(k - 1) * CELL;
                    if (best <= bd * bd) break;
                    const int xa = max(cx - k, 0), xb = min(cx + k, G - 1);
                    const int ya = max(cy - k, 0), yb = min(cy + k, G - 1);
                    for (int y = ya; y <= yb; ++y) {
                        if (y == cy - k || y == cy + k) {
                            scan(sst[y * G + xa], sst[y * G + xb + 1]);
                        } else {
                            if (cx - k >= 0) {
                                int cc = y * G + cx - k;
                                scan(sst[cc], sst[cc + 1]);
                            }
                            if (cx + k < G) {
                                int cc = y * G + cx + k;
                                scan(sst[cc], sst[cc + 1]);
                            }
                        }
                    }
                    best = __uint_as_float(mn & ~IDXMASK);
                }
            }
        }
    }

    // recover winner coordinates from SoA tile by index
    unsigned idx = mn & IDXMASK;
    const float* tw = reinterpret_cast<const float*>(tile4);
    int ww = ((idx >> 1) << 2) | (idx & 1);
    float wx = tw[ww], wy = tw[ww + 2];

    const float cA = dir ? 1.0f : subcoef[0];
    const float cB = dir ? 1.0f : subcoef[1];
    float contrib = fabsf(qx - wx) * cA + fabsf(qy - wy) * cB;

#pragma unroll
    for (int o = 16; o > 0; o >>= 1)
        contrib += __shfl_down_sync(0xffffffffu, contrib, o);
    if ((threadIdx.x & 31) == 0) red[threadIdx.x >> 5] = contrib;
    __syncthreads();
    if (threadIdx.x < 32) {
        float v = (threadIdx.x < TPB / 32) ? red[threadIdx.x] : 0.0f;
#pragma unroll
        for (int o = 4; o > 0; o >>= 1)
            v += __shfl_down_sync(0x000000ffu, v, o);
        if (threadIdx.x == 0) atomicAdd(out, v);
    }
}

extern "C" void kernel_launch(void* const* d_in, const int* in_sizes, int n_in,
                              void* d_out, int out_size)
{
    const float* preds   = (const float*)d_in[0];
    const float* targs   = (const float*)d_in[1];
    const float* subcoef = (const float*)d_in[2];
    float* out = (float*)d_out;

    bin_kernel  <<<NSB, TPB>>>(preds, targs, out);          // 128 blocks
    query_kernel<<<2 * Bc * QCH, TPB>>>(subcoef, out);      // 1024 blocks
}

// round 16
// speedup vs baseline: 1.0488x; 1.0488x over previous
#include <cuda_runtime.h>
#include <math_constants.h>

// NNLoss: bidirectional 2-D NN loss via uniform-grid spatial binning.
// Kernel 1: block-local bin; scatter staged in shared, coalesced global
//           write of SoA pairs {x0,x1,y0,y1}.
// Kernel 2: staged boxes (3x3 -> 9x9 -> rings), packed f32x2 distance math,
//           DUAL bits|index argmin accumulators (halved dep chain).

namespace {
constexpr int   Bc   = 64;
constexpr int   Nc   = 2048;
constexpr int   NSB  = 2 * Bc;            // (set, batch) segments = 128
constexpr int   G    = 64;
constexpr int   G2   = G * G;             // 4096 cells
constexpr int   SST  = G2 + 8;            // starts stride (padded)
constexpr float EXT  = 6.0f;
constexpr float CELL = 2.0f * EXT / G;    // 0.1875
constexpr float INVC = (float)G / (2.0f * EXT);
constexpr int   TPB  = 256;
constexpr int   QCH  = Nc / TPB;          // 8 query chunks per (dir,b)
constexpr unsigned IDXMASK = 2047u;       // low 11 bits carry point index
constexpr unsigned SENTINEL = 0x7F800000u | IDXMASK;  // +INF | idx-sat
}

__device__ unsigned short g_start[NSB * SST];      // exclusive cell starts (+total)
__device__ float4         g_sorted4[NSB * Nc / 2]; // SoA pairs {x0,x1,y0,y1}

__device__ __forceinline__ int cell_of(float v) {
    int c = __float2int_rd((v + EXT) * INVC);
    return min(G - 1, max(0, c));
}

// ---- packed f32x2 helpers ----
__device__ __forceinline__ unsigned long long pk2(float a, float b) {
    unsigned long long r;
    asm("mov.b64 %0, {%1, %2};" : "=l"(r) : "f"(a), "f"(b));
    return r;
}
__device__ __forceinline__ unsigned long long add2(unsigned long long a,
                                                   unsigned long long b) {
    unsigned long long r;
    asm("add.rn.f32x2 %0, %1, %2;" : "=l"(r) : "l"(a), "l"(b));
    return r;
}
__device__ __forceinline__ unsigned long long mul2(unsigned long long a,
                                                   unsigned long long b) {
    unsigned long long r;
    asm("mul.rn.f32x2 %0, %1, %2;" : "=l"(r) : "l"(a), "l"(b));
    return r;
}
__device__ __forceinline__ unsigned long long fma2(unsigned long long a,
                                                   unsigned long long b,
                                                   unsigned long long c) {
    unsigned long long r;
    asm("fma.rn.f32x2 %0, %1, %2, %3;" : "=l"(r) : "l"(a), "l"(b), "l"(c));
    return r;
}
__device__ __forceinline__ void unpk(unsigned long long v,
                                     unsigned& lo, unsigned& hi) {
    asm("mov.b64 {%0, %1}, %2;" : "=r"(lo), "=r"(hi) : "l"(v));
}

// ---------------- Kernel 1: block-local binning ----------------
__global__ __launch_bounds__(TPB)
void bin_kernel(const float* __restrict__ preds,
                const float* __restrict__ targs,
                float* __restrict__ out)
{
    __shared__ unsigned int scnt[G2];      // counts -> scatter cursors
    __shared__ float2 pts[Nc];
    __shared__ float4 ssorted[Nc / 2];     // staged SoA pairs
    __shared__ unsigned int part[TPB];

    const int sb  = blockIdx.x;            // set*64 + b
    const int set = sb >> 6;
    const int b   = sb & (Bc - 1);
    if (sb == 0 && threadIdx.x == 0) out[0] = 0.0f;

    const float4* src = reinterpret_cast<const float4*>(set ? targs : preds)
                      + (size_t)b * Nc;
#pragma unroll
    for (int i = 0; i < Nc / TPB; ++i) {
        float4 p = src[threadIdx.x + i * TPB];
        pts[threadIdx.x + i * TPB] = make_float2(p.x, p.y);
    }
#pragma unroll
    for (int i = 0; i < G2 / TPB; ++i)
        scnt[threadIdx.x + i * TPB] = 0u;
    __syncthreads();

#pragma unroll
    for (int i = 0; i < Nc / TPB; ++i) {
        float2 p = pts[threadIdx.x + i * TPB];
        atomicAdd(&scnt[cell_of(p.y) * G + cell_of(p.x)], 1u);
    }
    __syncthreads();

    // block exclusive scan of 4096 counters
    unsigned int v[16], sum = 0;
    const int base = threadIdx.x * 16;
#pragma unroll
    for (int i = 0; i < 16; ++i) { v[i] = scnt[base + i]; sum += v[i]; }
    part[threadIdx.x] = sum;
    __syncthreads();
    for (int off = 1; off < TPB; off <<= 1) {
        unsigned int a = (threadIdx.x >= off) ? part[threadIdx.x - off] : 0u;
        __syncthreads();
        if (threadIdx.x >= off) part[threadIdx.x] += a;
        __syncthreads();
    }
    unsigned int run = threadIdx.x ? part[threadIdx.x - 1] : 0u;
    unsigned short* st = g_start + sb * SST;
#pragma unroll
    for (int i = 0; i < 16; ++i) {
        scnt[base + i] = run;                       // scatter cursor
        st[base + i]   = (unsigned short)run;
        run += v[i];
    }
    if (threadIdx.x == TPB - 1) st[G2] = (unsigned short)run;   // 2048
    __syncthreads();

    // scatter into SHARED staging (SoA pair layout), then coalesced write
    float* sw = reinterpret_cast<float*>(ssorted);
#pragma unroll
    for (int i = 0; i < Nc / TPB; ++i) {
        float2 p = pts[threadIdx.x + i * TPB];
        unsigned int pos = atomicAdd(&scnt[cell_of(p.y) * G + cell_of(p.x)], 1u);
        int w = ((pos >> 1) << 2) | (pos & 1);
        sw[w]     = p.x;
        sw[w + 2] = p.y;
    }
    __syncthreads();

    float4* dst = g_sorted4 + (size_t)sb * (Nc / 2);
#pragma unroll
    for (int i = 0; i < (Nc / 2) / TPB; ++i)
        dst[threadIdx.x + i * TPB] = ssorted[threadIdx.x + i * TPB];
}

// ---------------- Kernel 2: staged-box query, packed math, dual argmin ----------------
__global__ __launch_bounds__(TPB)
void query_kernel(const float* __restrict__ subcoef, float* __restrict__ out)
{
    __shared__ float4 tile4[Nc / 2];             // SoA pairs {x0,x1,y0,y1}
    __shared__ unsigned short sst[G2 + 1];       // cell starts (point indices)
    __shared__ float red[TPB / 32];

    int bid = blockIdx.x;
    const int chunk = bid & (QCH - 1);  bid >>= 3;
    const int b     = bid & (Bc - 1);   bid >>= 6;
    const int dir   = bid;                       // 0: preds->targs, 1: targs->preds
    const int qsb = dir * Bc + b;                // query set (set0 = preds)
    const int dsb = (1 - dir) * Bc + b;          // db set

    {
        const float4* srcp = g_sorted4 + (size_t)dsb * (Nc / 2);
        for (int t = threadIdx.x; t < Nc / 2; t += TPB) tile4[t] = srcp[t];
        for (int t = threadIdx.x; t <= G2; t += TPB)    sst[t]  = g_start[dsb * SST + t];
    }
    __syncthreads();

    // query = own set's sorted point (order-invariant loss; cell-coherent lanes)
    float qx, qy;
    {
        const float* qw = reinterpret_cast<const float*>(
            g_sorted4 + (size_t)qsb * (Nc / 2));
        int i = chunk * TPB + threadIdx.x;
        int w = ((i >> 1) << 2) | (i & 1);
        qx = qw[w]; qy = qw[w + 2];
    }
    const int cx = cell_of(qx), cy = cell_of(qy);
    const unsigned long long nqx2 = pk2(-qx, -qx);
    const unsigned long long nqy2 = pk2(-qy, -qy);

    // DUAL packed argmin accumulators (independent carried chains)
    unsigned mn0 = SENTINEL, mn1 = SENTINEL;

    const ulonglong2* stile = reinterpret_cast<const ulonglong2*>(tile4);
    // paired span scan over point range [j, je), rounded OUTWARD to pair
    // bounds (extra points are genuine db points -> superset min, exact)
    auto scan = [&](int j, int je) {
        int p  = j >> 1;
        int pe = (je + 1) >> 1;
#pragma unroll 2
        for (; p < pe; ++p) {
            ulonglong2 t = stile[p];             // t.x={x0,x1}, t.y={y0,y1}
            unsigned long long dx = add2(t.x, nqx2);
            unsigned long long dy = add2(t.y, nqy2);
            unsigned long long s2 = fma2(dx, dx, mul2(dy, dy));
            unsigned s0, s1; unpk(s2, s0, s1);
            unsigned j0 = (unsigned)(p << 1);
            mn0 = min(mn0, (s0 & ~IDXMASK) | j0);
            mn1 = min(mn1, (s1 & ~IDXMASK) | (j0 + 1));
        }
    };
    auto box = [&](int r) {
        const int xa = max(cx - r, 0), xb = min(cx + r, G - 1);
        const int ya = max(cy - r, 0), yb = min(cy + r, G - 1);
        for (int y = ya; y <= yb; ++y)
            scan(sst[y * G + xa], sst[y * G + xb + 1]);
    };

    // stage 1: 3x3 box, straight-line 3 rows (clamped dups harmless)
    {
        const int xa = max(cx - 1, 0), xb = min(cx + 1, G - 1);
        const int y0 = max(cy - 1, 0), y2 = min(cy + 1, G - 1);
        scan(sst[y0 * G + xa], sst[y0 * G + xb + 1]);
        scan(sst[cy * G + xa], sst[cy * G + xb + 1]);
        scan(sst[y2 * G + xa], sst[y2 * G + xb + 1]);
    }

    // unscanned cells are Chebyshev >= 2 -> d >= CELL
    float best = __uint_as_float(min(mn0, mn1) & ~IDXMASK); // <= true best
    if (__any_sync(0xffffffffu, best > CELL * CELL)) {
        if (best > CELL * CELL) {
            // stage 2: 9x9 box. Unscanned -> Chebyshev >= 5 -> d >= 4*CELL.
            box(4);
            best = __uint_as_float(min(mn0, mn1) & ~IDXMASK);
            float b4 = 4.0f * CELL;
            if (best > b4 * b4) {
                // stage 3 (deep tail): rings from k=5
                for (int k = 5; k < G; ++k) {
                    float bd = (float)(k - 1) * CELL;
                    if (best <= bd * bd) break;
                    const int xa = max(cx - k, 0), xb = min(cx + k, G - 1);
                    const int ya = max(cy - k, 0), yb = min(cy + k, G - 1);
                    for (int y = ya; y <= yb; ++y) {
                        if (y == cy - k || y == cy + k) {
                            scan(sst[y * G + xa], sst[y * G + xb + 1]);
                        } else {
                            if (cx - k >= 0) {
                                int cc = y * G + cx - k;
                                scan(sst[cc], sst[cc + 1]);
                            }
                            if (cx + k < G) {
                                int cc = y * G + cx + k;
                                scan(sst[cc], sst[cc + 1]);
                            }
                        }
                    }
                    best = __uint_as_float(min(mn0, mn1) & ~IDXMASK);
                }
            }
        }
    }

    // recover winner coordinates from SoA tile by index
    unsigned idx = min(mn0, mn1) & IDXMASK;
    const float* tw = reinterpret_cast<const float*>(tile4);
    int ww = ((idx >> 1) << 2) | (idx & 1);
    float wx = tw[ww], wy = tw[ww + 2];

    const float cA = dir ? 1.0f : subcoef[0];
    const float cB = dir ? 1.0f : subcoef[1];
    float contrib = fabsf(qx - wx) * cA + fabsf(qy - wy) * cB;

#pragma unroll
    for (int o = 16; o > 0; o >>= 1)
        contrib += __shfl_down_sync(0xffffffffu, contrib, o);
    if ((threadIdx.x & 31) == 0) red[threadIdx.x >> 5] = contrib;
    __syncthreads();
    if (threadIdx.x < 32) {
        float v = (threadIdx.x < TPB / 32) ? red[threadIdx.x] : 0.0f;
#pragma unroll
        for (int o = 4; o > 0; o >>= 1)
            v += __shfl_down_sync(0x000000ffu, v, o);
        if (threadIdx.x == 0) atomicAdd(out, v);
    }
}

extern "C" void kernel_launch(void* const* d_in, const int* in_sizes, int n_in,
                              void* d_out, int out_size)
{
    const float* preds   = (const float*)d_in[0];
    const float* targs   = (const float*)d_in[1];
    const float* subcoef = (const float*)d_in[2];
    float* out = (float*)d_out;

    bin_kernel  <<<NSB, TPB>>>(preds, targs, out);          // 128 blocks
    query_kernel<<<2 * Bc * QCH, TPB>>>(subcoef, out);      // 1024 blocks
}